// round 1
// baseline (speedup 1.0000x reference)
#include <cuda_runtime.h>
#include <math.h>

// Scratch (device globals; no allocations allowed)
__device__ float g_logits[8 * 8 * 32 * 32];   // [b][n][h][w] pre-softmax logits, softmax'd in-place
__device__ float g_vsum[8 * 8 * 32 * 32];     // [b][n][x][y]
__device__ float g_wvsum[8 * 512];            // per-head row-sum of wv

// ---------------------------------------------------------------------------
// Kernel 0: wvsum[n][c] = sum_{d=0..63} wv[n*64+d][c]
// ---------------------------------------------------------------------------
__global__ void wvsum_kernel(const float* __restrict__ wv) {
    int n = blockIdx.x;        // 0..7
    int c = threadIdx.x;       // 0..511
    const float* base = wv + (size_t)(n * 64) * 512 + c;
    float s = 0.f;
#pragma unroll 8
    for (int d = 0; d < 64; ++d) s += base[d * 512];
    g_wvsum[n * 512 + c] = s;
}

// ---------------------------------------------------------------------------
// Kernel 1: fused Q/K GEMM + per-pixel per-head dot, plus vsum.
// Block: (pixel tile of 64) x (head). 128 threads.
// Thread tile: 4 pixels x 8 j's for both Q and K accumulators.
// ---------------------------------------------------------------------------
#define KC 16

__global__ void qk_kernel(const float* __restrict__ x,
                          const float* __restrict__ wq,
                          const float* __restrict__ wk) {
    const int tile = blockIdx.x;   // 0..127  (64 pixels each)
    const int head = blockIdx.y;   // 0..7
    const int tid  = threadIdx.x;  // 0..127
    const int tx   = tid & 15;     // pixel group: pixels tx*4 .. tx*4+3
    const int ty   = tid >> 4;     // j group: j ty*8 .. ty*8+7

    __shared__ float Xs[KC][64];
    __shared__ float Qs[KC][64];
    __shared__ float Ks[KC][64];
    __shared__ float Vs[KC];
    __shared__ float red[8][64];

    float accq[4][8];
    float acck[4][8];
    float accv[4] = {0.f, 0.f, 0.f, 0.f};
#pragma unroll
    for (int i = 0; i < 4; ++i)
#pragma unroll
        for (int j = 0; j < 8; ++j) { accq[i][j] = 0.f; acck[i][j] = 0.f; }

    const float* xblk  = x  + (size_t)tile * 64 * 512;
    const float* wqblk = wq + (size_t)head * 64 * 512;
    const float* wkblk = wk + (size_t)head * 64 * 512;
    const float* wvrow = g_wvsum + head * 512;

    for (int c0 = 0; c0 < 512; c0 += KC) {
        // Cooperative load: 64 rows x KC cols for X, Wq, Wk (transposed into smem)
#pragma unroll
        for (int pass = 0; pass < 2; ++pass) {
            int idx = pass * 128 + tid;     // 0..255
            int r   = idx >> 2;             // 0..63
            int cv  = idx & 3;              // float4 index within KC
            float4 xv = *(const float4*)(xblk  + r * 512 + c0 + cv * 4);
            float4 qv = *(const float4*)(wqblk + r * 512 + c0 + cv * 4);
            float4 kv = *(const float4*)(wkblk + r * 512 + c0 + cv * 4);
            Xs[cv*4+0][r] = xv.x; Xs[cv*4+1][r] = xv.y; Xs[cv*4+2][r] = xv.z; Xs[cv*4+3][r] = xv.w;
            Qs[cv*4+0][r] = qv.x; Qs[cv*4+1][r] = qv.y; Qs[cv*4+2][r] = qv.z; Qs[cv*4+3][r] = qv.w;
            Ks[cv*4+0][r] = kv.x; Ks[cv*4+1][r] = kv.y; Ks[cv*4+2][r] = kv.z; Ks[cv*4+3][r] = kv.w;
        }
        if (tid < KC) Vs[tid] = wvrow[c0 + tid];
        __syncthreads();

#pragma unroll
        for (int cc = 0; cc < KC; ++cc) {
            float a[4], qv[8], kv[8];
#pragma unroll
            for (int i = 0; i < 4; ++i) a[i] = Xs[cc][tx * 4 + i];
#pragma unroll
            for (int j = 0; j < 8; ++j) { qv[j] = Qs[cc][ty * 8 + j]; kv[j] = Ks[cc][ty * 8 + j]; }
#pragma unroll
            for (int i = 0; i < 4; ++i)
#pragma unroll
                for (int j = 0; j < 8; ++j) {
                    accq[i][j] = fmaf(a[i], qv[j], accq[i][j]);
                    acck[i][j] = fmaf(a[i], kv[j], acck[i][j]);
                }
            float vv = Vs[cc];
#pragma unroll
            for (int i = 0; i < 4; ++i) accv[i] = fmaf(a[i], vv, accv[i]);
        }
        __syncthreads();
    }

    // Partial per-pixel dot over this thread's 8 j's
#pragma unroll
    for (int i = 0; i < 4; ++i) {
        float p = 0.f;
#pragma unroll
        for (int j = 0; j < 8; ++j) p = fmaf(accq[i][j], acck[i][j], p);
        red[ty][tx * 4 + i] = p;
    }
    __syncthreads();

    // vsum (accv is identical across ty; ty==0 writes)
    if (ty == 0) {
#pragma unroll
        for (int i = 0; i < 4; ++i) {
            int p = tile * 64 + tx * 4 + i;     // pixel = b*1024 + h*32 + w
            int b = p >> 10;
            g_vsum[(b * 8 + head) * 1024 + (p & 1023)] = accv[i];
        }
    }

    // Reduce the 8 ty partials -> logits
    if (tid < 64) {
        float s = 0.f;
#pragma unroll
        for (int t = 0; t < 8; ++t) s += red[t][tid];
        int p = tile * 64 + tid;
        int b = p >> 10;
        g_logits[(b * 8 + head) * 1024 + (p & 1023)] = s;
    }
}

// ---------------------------------------------------------------------------
// Kernel 2: softmax over w (rows of 32), scale = 64^-0.5 = 0.125
// One warp per (b,n,h) row; 2048 rows total.
// ---------------------------------------------------------------------------
__global__ void softmax_kernel() {
    int warp = (blockIdx.x * blockDim.x + threadIdx.x) >> 5;  // 0..2047
    int lane = threadIdx.x & 31;
    float v = g_logits[warp * 32 + lane] * 0.125f;
    float m = v;
#pragma unroll
    for (int o = 16; o > 0; o >>= 1) m = fmaxf(m, __shfl_xor_sync(0xffffffffu, m, o));
    float e = __expf(v - m);
    float s = e;
#pragma unroll
    for (int o = 16; o > 0; o >>= 1) s += __shfl_xor_sync(0xffffffffu, s, o);
    g_logits[warp * 32 + lane] = e / s;
}

// ---------------------------------------------------------------------------
// Kernel 3: outer product store.
// out[b,n,h,w,x,y] = weights[b,n,h,w] * vsum[b,n,x,y]
// Block per (b,n,h) row r: writes 32 * 1024 floats = 128 KB.
// ---------------------------------------------------------------------------
__global__ void outer_kernel(float* __restrict__ out) {
    int r  = blockIdx.x;       // 0..2047 == (b*8+n)*32 + h
    int bn = r >> 5;
    int h  = r & 31;

    __shared__ float4 vs[256];
    __shared__ float  ws[32];
    vs[threadIdx.x] = ((const float4*)(g_vsum + bn * 1024))[threadIdx.x];
    if (threadIdx.x < 32) ws[threadIdx.x] = g_logits[bn * 1024 + h * 32 + threadIdx.x];
    __syncthreads();

    float4 v = vs[threadIdx.x];
    float4* o = (float4*)out + (size_t)r * 8192;
#pragma unroll
    for (int w = 0; w < 32; ++w) {
        float s = ws[w];
        float4 t = make_float4(s * v.x, s * v.y, s * v.z, s * v.w);
        o[w * 256 + threadIdx.x] = t;
    }
}

// ---------------------------------------------------------------------------
extern "C" void kernel_launch(void* const* d_in, const int* in_sizes, int n_in,
                              void* d_out, int out_size) {
    const float* x  = (const float*)d_in[0];
    const float* wq = (const float*)d_in[1];
    const float* wk = (const float*)d_in[2];
    const float* wv = (const float*)d_in[3];
    float* out = (float*)d_out;

    wvsum_kernel<<<8, 512>>>(wv);
    qk_kernel<<<dim3(128, 8), 128>>>(x, wq, wk);
    softmax_kernel<<<256, 256>>>();
    outer_kernel<<<2048, 256>>>(out);
}

// round 2
// speedup vs baseline: 1.0282x; 1.0282x over previous
#include <cuda_runtime.h>
#include <math.h>

// Scratch (device globals; no allocations allowed)
__device__ float g_logits[8 * 8 * 32 * 32];   // [b][n][h][w] logits -> softmax'd in place
__device__ float g_vsum[8 * 8 * 32 * 32];     // [b][n][x][y]
__device__ float g_wvsum[8 * 512];            // per-head row-sum of wv

// ---------------------------------------------------------------------------
// Kernel 0: wvsum[n][c] = sum_{d=0..63} wv[n*64+d][c]
// ---------------------------------------------------------------------------
__global__ void wvsum_kernel(const float* __restrict__ wv) {
    int n = blockIdx.x;        // 0..7
    int c = threadIdx.x;       // 0..511
    const float* base = wv + (size_t)(n * 64) * 512 + c;
    float s = 0.f;
#pragma unroll 8
    for (int d = 0; d < 64; ++d) s += base[d * 512];
    g_wvsum[n * 512 + c] = s;
}

// ---------------------------------------------------------------------------
// Kernel 1: fused Q/K GEMM + per-pixel per-head dot, plus vsum.
// f32x2-packed FFMA2 inner loop (packs the j dimension in pairs).
// Block: (pixel tile of 64) x (head). 128 threads.
// Thread tile: 4 pixels x 8 j's (4 packed pairs) for Q and K accumulators.
// ---------------------------------------------------------------------------
#define KC 16

__device__ __forceinline__ unsigned long long pack2(float lo, float hi) {
    unsigned long long r;
    asm("mov.b64 %0, {%1, %2};" : "=l"(r) : "f"(lo), "f"(hi));
    return r;
}
__device__ __forceinline__ void unpack2(unsigned long long v, float& lo, float& hi) {
    asm("mov.b64 {%0, %1}, %2;" : "=f"(lo), "=f"(hi) : "l"(v));
}
__device__ __forceinline__ unsigned long long fma2(unsigned long long a,
                                                   unsigned long long b,
                                                   unsigned long long c) {
    unsigned long long d;
    asm("fma.rn.f32x2 %0, %1, %2, %3;" : "=l"(d) : "l"(a), "l"(b), "l"(c));
    return d;
}

__global__ void qk_kernel(const float* __restrict__ x,
                          const float* __restrict__ wq,
                          const float* __restrict__ wk) {
    const int tile = blockIdx.x;   // 0..127  (64 pixels each)
    const int head = blockIdx.y;   // 0..7
    const int tid  = threadIdx.x;  // 0..127
    const int tx   = tid & 15;     // pixel group: pixels tx*4 .. tx*4+3
    const int ty   = tid >> 4;     // j group: j ty*8 .. ty*8+7

    __shared__ __align__(16) float Xs[KC][64];
    __shared__ __align__(16) float Qs[KC][64];
    __shared__ __align__(16) float Ks[KC][64];
    __shared__ float Vs[KC];
    __shared__ float red[8][64];

    unsigned long long accq[4][4];   // [pixel][j-pair] packed f32x2
    unsigned long long acck[4][4];
    float accv[4] = {0.f, 0.f, 0.f, 0.f};
#pragma unroll
    for (int i = 0; i < 4; ++i)
#pragma unroll
        for (int j = 0; j < 4; ++j) { accq[i][j] = 0ull; acck[i][j] = 0ull; }

    const float* xblk  = x  + (size_t)tile * 64 * 512;
    const float* wqblk = wq + (size_t)head * 64 * 512;
    const float* wkblk = wk + (size_t)head * 64 * 512;
    const float* wvrow = g_wvsum + head * 512;

    for (int c0 = 0; c0 < 512; c0 += KC) {
        // Cooperative load: 64 rows x KC cols for X, Wq, Wk (transposed into smem)
#pragma unroll
        for (int pass = 0; pass < 2; ++pass) {
            int idx = pass * 128 + tid;     // 0..255
            int r   = idx >> 2;             // 0..63
            int cv  = idx & 3;              // float4 index within KC
            float4 xv = *(const float4*)(xblk  + r * 512 + c0 + cv * 4);
            float4 qv = *(const float4*)(wqblk + r * 512 + c0 + cv * 4);
            float4 kv = *(const float4*)(wkblk + r * 512 + c0 + cv * 4);
            Xs[cv*4+0][r] = xv.x; Xs[cv*4+1][r] = xv.y; Xs[cv*4+2][r] = xv.z; Xs[cv*4+3][r] = xv.w;
            Qs[cv*4+0][r] = qv.x; Qs[cv*4+1][r] = qv.y; Qs[cv*4+2][r] = qv.z; Qs[cv*4+3][r] = qv.w;
            Ks[cv*4+0][r] = kv.x; Ks[cv*4+1][r] = kv.y; Ks[cv*4+2][r] = kv.z; Ks[cv*4+3][r] = kv.w;
        }
        if (tid < KC) Vs[tid] = wvrow[c0 + tid];
        __syncthreads();

#pragma unroll
        for (int cc = 0; cc < KC; ++cc) {
            float a[4];
            unsigned long long a2[4];
#pragma unroll
            for (int i = 0; i < 4; ++i) {
                a[i]  = Xs[cc][tx * 4 + i];
                a2[i] = pack2(a[i], a[i]);
            }
            // packed (j, j+1) pairs — contiguous in smem, 8-byte LDS
            unsigned long long q2[4], k2[4];
#pragma unroll
            for (int jj = 0; jj < 4; ++jj) {
                float2 qv = *(const float2*)&Qs[cc][ty * 8 + jj * 2];
                float2 kv = *(const float2*)&Ks[cc][ty * 8 + jj * 2];
                q2[jj] = pack2(qv.x, qv.y);
                k2[jj] = pack2(kv.x, kv.y);
            }
#pragma unroll
            for (int i = 0; i < 4; ++i)
#pragma unroll
                for (int jj = 0; jj < 4; ++jj) {
                    accq[i][jj] = fma2(a2[i], q2[jj], accq[i][jj]);
                    acck[i][jj] = fma2(a2[i], k2[jj], acck[i][jj]);
                }
            float vv = Vs[cc];
#pragma unroll
            for (int i = 0; i < 4; ++i) accv[i] = fmaf(a[i], vv, accv[i]);
        }
        __syncthreads();
    }

    // Partial per-pixel dot over this thread's 8 j's (4 packed pairs)
#pragma unroll
    for (int i = 0; i < 4; ++i) {
        float p = 0.f;
#pragma unroll
        for (int jj = 0; jj < 4; ++jj) {
            float ql, qh, kl, kh;
            unpack2(accq[i][jj], ql, qh);
            unpack2(acck[i][jj], kl, kh);
            p = fmaf(ql, kl, p);
            p = fmaf(qh, kh, p);
        }
        red[ty][tx * 4 + i] = p;
    }
    __syncthreads();

    // vsum (accv identical across ty; ty==0 writes)
    if (ty == 0) {
#pragma unroll
        for (int i = 0; i < 4; ++i) {
            int p = tile * 64 + tx * 4 + i;     // pixel = b*1024 + h*32 + w
            int b = p >> 10;
            g_vsum[(b * 8 + head) * 1024 + (p & 1023)] = accv[i];
        }
    }

    // Reduce the 8 ty partials -> logits
    if (tid < 64) {
        float s = 0.f;
#pragma unroll
        for (int t = 0; t < 8; ++t) s += red[t][tid];
        int p = tile * 64 + tid;
        int b = p >> 10;
        g_logits[(b * 8 + head) * 1024 + (p & 1023)] = s;
    }
}

// ---------------------------------------------------------------------------
// Kernel 2: softmax over w (rows of 32), scale = 64^-0.5 = 0.125
// ---------------------------------------------------------------------------
__global__ void softmax_kernel() {
    int warp = (blockIdx.x * blockDim.x + threadIdx.x) >> 5;  // 0..2047
    int lane = threadIdx.x & 31;
    float v = g_logits[warp * 32 + lane] * 0.125f;
    float m = v;
#pragma unroll
    for (int o = 16; o > 0; o >>= 1) m = fmaxf(m, __shfl_xor_sync(0xffffffffu, m, o));
    float e = __expf(v - m);
    float s = e;
#pragma unroll
    for (int o = 16; o > 0; o >>= 1) s += __shfl_xor_sync(0xffffffffu, s, o);
    g_logits[warp * 32 + lane] = e / s;
}

// ---------------------------------------------------------------------------
// Kernel 3: outer product store (streaming stores; data is write-once).
// out[b,n,h,w,x,y] = weights[b,n,h,w] * vsum[b,n,x,y]
// ---------------------------------------------------------------------------
__global__ void outer_kernel(float* __restrict__ out) {
    int r  = blockIdx.x;       // 0..2047 == (b*8+n)*32 + h
    int bn = r >> 5;
    int h  = r & 31;

    __shared__ float4 vs[256];
    __shared__ float  ws[32];
    vs[threadIdx.x] = ((const float4*)(g_vsum + bn * 1024))[threadIdx.x];
    if (threadIdx.x < 32) ws[threadIdx.x] = g_logits[bn * 1024 + h * 32 + threadIdx.x];
    __syncthreads();

    float4 v = vs[threadIdx.x];
    float4* o = (float4*)out + (size_t)r * 8192;
#pragma unroll
    for (int w = 0; w < 32; ++w) {
        float s = ws[w];
        float4 t = make_float4(s * v.x, s * v.y, s * v.z, s * v.w);
        __stcs(&o[w * 256 + threadIdx.x], t);
    }
}

// ---------------------------------------------------------------------------
extern "C" void kernel_launch(void* const* d_in, const int* in_sizes, int n_in,
                              void* d_out, int out_size) {
    const float* x  = (const float*)d_in[0];
    const float* wq = (const float*)d_in[1];
    const float* wk = (const float*)d_in[2];
    const float* wv = (const float*)d_in[3];
    float* out = (float*)d_out;

    wvsum_kernel<<<8, 512>>>(wv);
    qk_kernel<<<dim3(128, 8), 128>>>(x, wq, wk);
    softmax_kernel<<<256, 256>>>();
    outer_kernel<<<2048, 256>>>(out);
}

// round 4
// speedup vs baseline: 1.7159x; 1.6688x over previous
#include <cuda_runtime.h>
#include <cuda_bf16.h>
#include <stdint.h>
#include <math.h>

// ---------------------------------------------------------------- scratch
__device__ float g_logits[8 * 8 * 32 * 32];   // [b][n][h][w], softmax'd in place
__device__ float g_vsum[8 * 8 * 32 * 32];     // [b][n][x][y]
__device__ float g_wvsum[8 * 512];

// ---------------------------------------------------------------- helpers
__device__ __forceinline__ uint32_t smem_u32(const void* p) {
    uint32_t a;
    asm("{ .reg .u64 t; cvta.to.shared.u64 t, %1; cvt.u32.u64 %0, t; }" : "=r"(a) : "l"(p));
    return a;
}
__device__ __forceinline__ void ldsm4(uint32_t* r, uint32_t addr) {
    asm volatile("ldmatrix.sync.aligned.m8n8.x4.shared.b16 {%0,%1,%2,%3}, [%4];"
                 : "=r"(r[0]), "=r"(r[1]), "=r"(r[2]), "=r"(r[3]) : "r"(addr));
}
__device__ __forceinline__ void mma16816(float* d, const uint32_t* a, const uint32_t* b) {
    asm volatile(
        "mma.sync.aligned.m16n8k16.row.col.f32.bf16.bf16.f32 "
        "{%0,%1,%2,%3}, {%4,%5,%6,%7}, {%8,%9}, {%0,%1,%2,%3};"
        : "+f"(d[0]), "+f"(d[1]), "+f"(d[2]), "+f"(d[3])
        : "r"(a[0]), "r"(a[1]), "r"(a[2]), "r"(a[3]), "r"(b[0]), "r"(b[1]));
}
__device__ __forceinline__ uint32_t pack_hi(float a, float b, float& la, float& lb) {
    __nv_bfloat16 ha = __float2bfloat16(a), hb = __float2bfloat16(b);
    la = a - __bfloat162float(ha);
    lb = b - __bfloat162float(hb);
    return (uint32_t)__bfloat16_as_ushort(ha) | ((uint32_t)__bfloat16_as_ushort(hb) << 16);
}
__device__ __forceinline__ uint32_t pack_bf(float a, float b) {
    __nv_bfloat16 ha = __float2bfloat16(a), hb = __float2bfloat16(b);
    return (uint32_t)__bfloat16_as_ushort(ha) | ((uint32_t)__bfloat16_as_ushort(hb) << 16);
}

// ---------------------------------------------------------------- kernel: wvsum
__global__ void wvsum_kernel(const float* __restrict__ wv) {
    int n = blockIdx.x, c = threadIdx.x;
    const float* base = wv + (size_t)(n * 64) * 512 + c;
    float s = 0.f;
#pragma unroll 8
    for (int d = 0; d < 64; ++d) s += base[d * 512];
    g_wvsum[n * 512 + c] = s;
}

// ---------------------------------------------------------------- kernel: vsum (fp32)
__global__ void vsum_kernel(const float* __restrict__ x) {
    int p = blockIdx.x * 8 + (threadIdx.x >> 5);
    int lane = threadIdx.x & 31;
    const float4* xr = (const float4*)(x + (size_t)p * 512);
    float4 xv[4];
#pragma unroll
    for (int t = 0; t < 4; ++t) xv[t] = xr[lane * 4 + t];
    float acc[8];
#pragma unroll
    for (int n = 0; n < 8; ++n) {
        const float4* wr = (const float4*)(g_wvsum + n * 512);
        float s = 0.f;
#pragma unroll
        for (int t = 0; t < 4; ++t) {
            float4 w = wr[lane * 4 + t];
            s = fmaf(xv[t].x, w.x, s); s = fmaf(xv[t].y, w.y, s);
            s = fmaf(xv[t].z, w.z, s); s = fmaf(xv[t].w, w.w, s);
        }
#pragma unroll
        for (int o = 16; o > 0; o >>= 1) s += __shfl_xor_sync(0xffffffffu, s, o);
        acc[n] = s;
    }
    if (lane < 8) {
        float v = acc[0];
#pragma unroll
        for (int n = 1; n < 8; ++n) if (lane == n) v = acc[n];
        int b = p >> 10, pos = p & 1023;
        g_vsum[(b * 8 + lane) * 1024 + pos] = v;
    }
}

// ---------------------------------------------------------------- kernel: QK via mma.sync
// block = (128-pixel tile) x (head). 256 threads / 8 warps, each warp owns 16 rows.
// smem bf16 tiles, row stride 72 elems (144 B) for conflict-free ldmatrix.
static constexpr int RS   = 144;            // row stride bytes
static constexpr int XH_O = 0;              // X hi  (128 x 72) : 18432 B
static constexpr int XL_O = 18432;          // X lo
static constexpr int QH_O = 36864;          // Wq hi (64 x 72)  : 9216 B
static constexpr int QL_O = 46080;
static constexpr int KH_O = 55296;
static constexpr int KL_O = 64512;
static constexpr int SM_TOTAL = 73728;

__global__ void __launch_bounds__(256, 2)
qk_kernel(const float* __restrict__ x,
          const float* __restrict__ wq,
          const float* __restrict__ wk) {
    extern __shared__ char smem[];
    const uint32_t sb = smem_u32(smem);
    const int tid  = threadIdx.x;
    const int lane = tid & 31;
    const int wid  = tid >> 5;
    const int tile = blockIdx.x;      // 0..63
    const int head = blockIdx.y;      // 0..7
    const int pix0 = tile * 128;

    // ldmatrix lane addressing (bytes, relative to array base)
    const uint32_t a_off = sb + (uint32_t)(wid * 16 + (lane & 15)) * RS + ((lane >> 4) << 4);
    const uint32_t b_row = (lane & 7) + ((lane >> 4) << 3);          // 0..15
    const uint32_t b_off = sb + b_row * RS + (((lane >> 3) & 1) << 4);

    float accQ[8][4], accK[8][4];
#pragma unroll
    for (int i = 0; i < 8; ++i)
#pragma unroll
        for (int j = 0; j < 4; ++j) { accQ[i][j] = 0.f; accK[i][j] = 0.f; }

    const float* xblk = x + (size_t)pix0 * 512;
    const float* qblk = wq + (size_t)head * 64 * 512;
    const float* kblk = wk + (size_t)head * 64 * 512;

    for (int ch = 0; ch < 8; ++ch) {
        const int c0 = ch * 64;
        // ---- X tile: 128 rows x 64 cols fp32 -> hi/lo bf16
#pragma unroll
        for (int i = 0; i < 8; ++i) {
            int idx = tid + i * 256;               // 0..2047
            int r = idx >> 4, c4 = idx & 15;
            float4 v = *(const float4*)(xblk + r * 512 + c0 + c4 * 4);
            float l0, l1, l2, l3;
            uint32_t h01 = pack_hi(v.x, v.y, l0, l1);
            uint32_t h23 = pack_hi(v.z, v.w, l2, l3);
            char* base = smem + (size_t)r * RS + c4 * 8;
            *(uint2*)(base + XH_O) = make_uint2(h01, h23);
            *(uint2*)(base + XL_O) = make_uint2(pack_bf(l0, l1), pack_bf(l2, l3));
        }
        // ---- W tiles: 64 rows x 64 cols each
#pragma unroll
        for (int i = 0; i < 4; ++i) {
            int idx = tid + i * 256;               // 0..1023
            int r = idx >> 4, c4 = idx & 15;
            char* base = smem + (size_t)r * RS + c4 * 8;
            {
                float4 v = *(const float4*)(qblk + r * 512 + c0 + c4 * 4);
                float l0, l1, l2, l3;
                uint32_t h01 = pack_hi(v.x, v.y, l0, l1);
                uint32_t h23 = pack_hi(v.z, v.w, l2, l3);
                *(uint2*)(base + QH_O) = make_uint2(h01, h23);
                *(uint2*)(base + QL_O) = make_uint2(pack_bf(l0, l1), pack_bf(l2, l3));
            }
            {
                float4 v = *(const float4*)(kblk + r * 512 + c0 + c4 * 4);
                float l0, l1, l2, l3;
                uint32_t h01 = pack_hi(v.x, v.y, l0, l1);
                uint32_t h23 = pack_hi(v.z, v.w, l2, l3);
                *(uint2*)(base + KH_O) = make_uint2(h01, h23);
                *(uint2*)(base + KL_O) = make_uint2(pack_bf(l0, l1), pack_bf(l2, l3));
            }
        }
        __syncthreads();

#pragma unroll
        for (int ks = 0; ks < 4; ++ks) {
            const uint32_t ko = ks * 32;          // 16 bf16 = 32 B
            uint32_t ah[4], al[4];
            ldsm4(ah, a_off + XH_O + ko);
            ldsm4(al, a_off + XL_O + ko);
#pragma unroll
            for (int np = 0; np < 4; ++np) {
                const uint32_t off = b_off + np * (16 * RS) + ko;
                uint32_t bh[4], bl[4];
                ldsm4(bh, off + QH_O);
                ldsm4(bl, off + QL_O);
                mma16816(accQ[np * 2],     ah, bh);
                mma16816(accQ[np * 2],     ah, bl);
                mma16816(accQ[np * 2],     al, bh);
                mma16816(accQ[np * 2 + 1], ah, bh + 2);
                mma16816(accQ[np * 2 + 1], ah, bl + 2);
                mma16816(accQ[np * 2 + 1], al, bh + 2);
                ldsm4(bh, off + KH_O);
                ldsm4(bl, off + KL_O);
                mma16816(accK[np * 2],     ah, bh);
                mma16816(accK[np * 2],     ah, bl);
                mma16816(accK[np * 2],     al, bh);
                mma16816(accK[np * 2 + 1], ah, bh + 2);
                mma16816(accK[np * 2 + 1], ah, bl + 2);
                mma16816(accK[np * 2 + 1], al, bh + 2);
            }
        }
        __syncthreads();
    }

    // ---- epilogue: per-pixel dot over 64 j's, straight off the fragments
    float plo = 0.f, phi = 0.f;
#pragma unroll
    for (int nt = 0; nt < 8; ++nt) {
        plo = fmaf(accQ[nt][0], accK[nt][0], plo);
        plo = fmaf(accQ[nt][1], accK[nt][1], plo);
        phi = fmaf(accQ[nt][2], accK[nt][2], phi);
        phi = fmaf(accQ[nt][3], accK[nt][3], phi);
    }
    plo += __shfl_xor_sync(0xffffffffu, plo, 1);
    plo += __shfl_xor_sync(0xffffffffu, plo, 2);
    phi += __shfl_xor_sync(0xffffffffu, phi, 1);
    phi += __shfl_xor_sync(0xffffffffu, phi, 2);
    if ((lane & 3) == 0) {
        int r0 = wid * 16 + (lane >> 2);
        int p0 = pix0 + r0;
        int p1 = p0 + 8;
        int b0 = p0 >> 10, b1 = p1 >> 10;
        g_logits[(b0 * 8 + head) * 1024 + (p0 & 1023)] = plo;
        g_logits[(b1 * 8 + head) * 1024 + (p1 & 1023)] = phi;
    }
}

// ---------------------------------------------------------------- kernel: softmax
__global__ void softmax_kernel() {
    int warp = (blockIdx.x * blockDim.x + threadIdx.x) >> 5;
    int lane = threadIdx.x & 31;
    float v = g_logits[warp * 32 + lane] * 0.125f;
    float m = v;
#pragma unroll
    for (int o = 16; o > 0; o >>= 1) m = fmaxf(m, __shfl_xor_sync(0xffffffffu, m, o));
    float e = __expf(v - m);
    float s = e;
#pragma unroll
    for (int o = 16; o > 0; o >>= 1) s += __shfl_xor_sync(0xffffffffu, s, o);
    g_logits[warp * 32 + lane] = e / s;
}

// ---------------------------------------------------------------- kernel: outer store
__global__ void outer_kernel(float* __restrict__ out) {
    int r = blockIdx.x;        // (b*8+n)*32 + h
    int bn = r >> 5;
    int h = r & 31;
    __shared__ float4 vs[256];
    __shared__ float ws[32];
    vs[threadIdx.x] = ((const float4*)(g_vsum + bn * 1024))[threadIdx.x];
    if (threadIdx.x < 32) ws[threadIdx.x] = g_logits[bn * 1024 + h * 32 + threadIdx.x];
    __syncthreads();
    float4 v = vs[threadIdx.x];
    float4* o = (float4*)out + (size_t)r * 8192;
#pragma unroll
    for (int w = 0; w < 32; ++w) {
        float s = ws[w];
        float4 t = make_float4(s * v.x, s * v.y, s * v.z, s * v.w);
        __stcs(&o[w * 256 + threadIdx.x], t);
    }
}

// ----------------------------------------------------------------
extern "C" void kernel_launch(void* const* d_in, const int* in_sizes, int n_in,
                              void* d_out, int out_size) {
    const float* x  = (const float*)d_in[0];
    const float* wq = (const float*)d_in[1];
    const float* wk = (const float*)d_in[2];
    const float* wv = (const float*)d_in[3];
    float* out = (float*)d_out;

    static bool attr_set = false;
    if (!attr_set) {
        cudaFuncSetAttribute(qk_kernel, cudaFuncAttributeMaxDynamicSharedMemorySize, SM_TOTAL);
        attr_set = true;
    }

    wvsum_kernel<<<8, 512>>>(wv);
    vsum_kernel<<<1024, 256>>>(x);
    qk_kernel<<<dim3(64, 8), 256, SM_TOTAL>>>(x, wq, wk);
    softmax_kernel<<<256, 256>>>();
    outer_kernel<<<2048, 256>>>(out);
}